// round 3
// baseline (speedup 1.0000x reference)
#include <cuda_runtime.h>
#include <cstdint>
#include <cstddef>

#define NN 50000
#define EE 800000
#define RR 8
#define FF 128
#define HH 128
#define CC 64

// ---------------- static device scratch (no allocations allowed) ----------------
__device__ float g_xr[(size_t)NN * RR * HH];   // per-relation transformed features
__device__ float g_h1[(size_t)NN * HH];
__device__ float g_h2[(size_t)NN * HH];
__device__ float g_qx[NN * RR];
__device__ float g_kx[NN * RR];
__device__ float g_wq[RR * FF];
__device__ float g_wk[RR * FF];
__device__ int   g_rowptr[NN + 1];
__device__ int   g_cursor[NN];
__device__ int   g_deg[NN];
__device__ int   g_srcet[EE];                  // src*8 + etype, sorted by dst

// ---------------- CSR build ----------------
__global__ void k_zero_deg() {
    int i = blockIdx.x * blockDim.x + threadIdx.x;
    if (i < NN) g_deg[i] = 0;
}

__global__ void k_count(const int* __restrict__ ei) {
    int e = blockIdx.x * blockDim.x + threadIdx.x;
    if (e < EE) atomicAdd(&g_deg[ei[EE + e]], 1);
}

__global__ void k_scan() {
    __shared__ int s[1024];
    __shared__ int carry;
    if (threadIdx.x == 0) { carry = 0; g_rowptr[0] = 0; }
    __syncthreads();
    for (int base = 0; base < NN; base += 1024) {
        int i = base + threadIdx.x;
        int v = (i < NN) ? g_deg[i] : 0;
        s[threadIdx.x] = v;
        __syncthreads();
        for (int off = 1; off < 1024; off <<= 1) {
            int t = (threadIdx.x >= off) ? s[threadIdx.x - off] : 0;
            __syncthreads();
            s[threadIdx.x] += t;
            __syncthreads();
        }
        int incl = s[threadIdx.x];
        if (i < NN) {
            g_rowptr[i + 1] = carry + incl;
            g_cursor[i]     = carry + incl - v;
        }
        __syncthreads();
        if (threadIdx.x == 1023) carry += s[1023];
        __syncthreads();
    }
}

__global__ void k_fill(const int* __restrict__ ei, const int* __restrict__ et) {
    int e = blockIdx.x * blockDim.x + threadIdx.x;
    if (e < EE) {
        int d = ei[EE + e];
        int pos = atomicAdd(&g_cursor[d], 1);
        g_srcet[pos] = ei[e] * RR + et[e];
    }
}

// ---------------- wq[r,f] = W[r,f,:].q ;  wk[r,f] = W[r,f,:].k ----------------
__global__ void k_wqk(const float* __restrict__ W, const float* __restrict__ q,
                      const float* __restrict__ kk) {
    int warp = (blockIdx.x * blockDim.x + threadIdx.x) >> 5;
    int lane = threadIdx.x & 31;
    if (warp >= RR * FF) return;
    const float* wrow = W + (size_t)warp * HH;
    float sq = 0.f, sk = 0.f;
#pragma unroll
    for (int i = 0; i < 4; i++) {
        int h = lane + 32 * i;
        float wv = wrow[h];
        sq += wv * q[h];
        sk += wv * kk[h];
    }
#pragma unroll
    for (int o = 16; o > 0; o >>= 1) {
        sq += __shfl_xor_sync(~0u, sq, o);
        sk += __shfl_xor_sync(~0u, sk, o);
    }
    if (lane == 0) { g_wq[warp] = sq; g_wk[warp] = sk; }
}

// ---------------- qx[n,r] = x[n,:].wq[r,:] (exact fp32 scores) ----------------
__global__ void __launch_bounds__(256) k_qx(const float* __restrict__ x) {
    __shared__ float swq[RR * FF];
    __shared__ float swk[RR * FF];
    for (int i = threadIdx.x; i < RR * FF; i += 256) { swq[i] = g_wq[i]; swk[i] = g_wk[i]; }
    __syncthreads();
    int node = blockIdx.x * 8 + (threadIdx.x >> 5);
    int lane = threadIdx.x & 31;
    if (node >= NN) return;
    float4 xv = ((const float4*)(x + (size_t)node * FF))[lane];
#pragma unroll
    for (int r = 0; r < RR; r++) {
        float4 a = ((const float4*)(swq + r * FF))[lane];
        float4 b = ((const float4*)(swk + r * FF))[lane];
        float sq = xv.x * a.x + xv.y * a.y + xv.z * a.z + xv.w * a.w;
        float sk = xv.x * b.x + xv.y * b.y + xv.z * b.z + xv.w * b.w;
#pragma unroll
        for (int o = 16; o > 0; o >>= 1) {
            sq += __shfl_xor_sync(~0u, sq, o);
            sk += __shfl_xor_sync(~0u, sk, o);
        }
        if (lane == 0) { g_qx[node * RR + r] = sq; g_kx[node * RR + r] = sk; }
    }
}

// ---------------- batched GEMM: xr[n, r, :] = x[n,:] @ W[r] (tf32 mma) ----------------
__device__ __forceinline__ unsigned f2tf(float f) {
    unsigned u;
    asm("cvt.rna.tf32.f32 %0, %1;" : "=r"(u) : "f"(f));
    return u;
}

__global__ void __launch_bounds__(256) k_gemm(const float* __restrict__ X,
                                              const float* __restrict__ W) {
    __shared__ float sX[128][36];   // bank-conflict-free for A-frag pattern
    __shared__ float sW[32][136];   // bank-conflict-free for B-frag pattern
    int r  = blockIdx.y;
    int m0 = blockIdx.x * 128;
    int tid = threadIdx.x;
    int lane = tid & 31, warp = tid >> 5;
    int wm = warp & 3, wn = warp >> 2;      // 4x2 warp grid: 128 rows x 128 cols
    float acc[2][8][4];
#pragma unroll
    for (int i = 0; i < 2; i++)
#pragma unroll
        for (int j = 0; j < 8; j++)
#pragma unroll
            for (int c = 0; c < 4; c++) acc[i][j][c] = 0.f;

    const float* Wr = W + (size_t)r * FF * HH;
    int q4 = lane & 3, g8 = lane >> 2;

    for (int kc = 0; kc < 4; kc++) {
        // stage X tile 128x32 (tf32-rounded)
#pragma unroll
        for (int i = 0; i < 4; i++) {
            int id = tid + i * 256;          // float4 id, 1024 total
            int row = id >> 3, c4 = id & 7;
            float4 v = make_float4(0.f, 0.f, 0.f, 0.f);
            if (m0 + row < NN)
                v = *(const float4*)(X + (size_t)(m0 + row) * FF + kc * 32 + c4 * 4);
            sX[row][c4 * 4 + 0] = __uint_as_float(f2tf(v.x));
            sX[row][c4 * 4 + 1] = __uint_as_float(f2tf(v.y));
            sX[row][c4 * 4 + 2] = __uint_as_float(f2tf(v.z));
            sX[row][c4 * 4 + 3] = __uint_as_float(f2tf(v.w));
        }
        // stage W tile 32x128 (tf32-rounded)
#pragma unroll
        for (int i = 0; i < 4; i++) {
            int id = tid + i * 256;          // float4 id, 1024 total
            int row = id >> 5, c4 = id & 31;
            float4 v = *(const float4*)(Wr + (size_t)(kc * 32 + row) * HH + c4 * 4);
            sW[row][c4 * 4 + 0] = __uint_as_float(f2tf(v.x));
            sW[row][c4 * 4 + 1] = __uint_as_float(f2tf(v.y));
            sW[row][c4 * 4 + 2] = __uint_as_float(f2tf(v.z));
            sW[row][c4 * 4 + 3] = __uint_as_float(f2tf(v.w));
        }
        __syncthreads();
#pragma unroll
        for (int k8 = 0; k8 < 4; k8++) {
            int kk = k8 * 8;
            unsigned a[2][4];
#pragma unroll
            for (int mt = 0; mt < 2; mt++) {
                int r0 = wm * 32 + mt * 16 + g8;
                a[mt][0] = __float_as_uint(sX[r0][kk + q4]);
                a[mt][1] = __float_as_uint(sX[r0 + 8][kk + q4]);
                a[mt][2] = __float_as_uint(sX[r0][kk + q4 + 4]);
                a[mt][3] = __float_as_uint(sX[r0 + 8][kk + q4 + 4]);
            }
#pragma unroll
            for (int nt = 0; nt < 8; nt++) {
                int nc = wn * 64 + nt * 8 + g8;
                unsigned b0 = __float_as_uint(sW[kk + q4][nc]);
                unsigned b1 = __float_as_uint(sW[kk + q4 + 4][nc]);
#pragma unroll
                for (int mt = 0; mt < 2; mt++) {
                    asm volatile(
                        "mma.sync.aligned.m16n8k8.row.col.f32.tf32.tf32.f32 "
                        "{%0,%1,%2,%3}, {%4,%5,%6,%7}, {%8,%9}, {%0,%1,%2,%3};"
                        : "+f"(acc[mt][nt][0]), "+f"(acc[mt][nt][1]),
                          "+f"(acc[mt][nt][2]), "+f"(acc[mt][nt][3])
                        : "r"(a[mt][0]), "r"(a[mt][1]), "r"(a[mt][2]), "r"(a[mt][3]),
                          "r"(b0), "r"(b1));
                }
            }
        }
        __syncthreads();
    }
    // epilogue: xr[(n*R + r)*H + h]
#pragma unroll
    for (int mt = 0; mt < 2; mt++) {
        int grow = m0 + wm * 32 + mt * 16 + g8;
#pragma unroll
        for (int nt = 0; nt < 8; nt++) {
            int col = wn * 64 + nt * 8 + q4 * 2;
            size_t base = ((size_t)grow * RR + r) * HH + col;
            if (grow < NN)
                *(float2*)&g_xr[base] = make_float2(acc[mt][nt][0], acc[mt][nt][1]);
            if (grow + 8 < NN)
                *(float2*)&g_xr[base + (size_t)8 * RR * HH] =
                    make_float2(acc[mt][nt][2], acc[mt][nt][3]);
        }
    }
}

// ------- fused per-node: leaky scores -> segment softmax -> weighted gather -> +b, relu -------
__global__ void __launch_bounds__(256) k_agg(const float* __restrict__ bias,
                                             float* __restrict__ hout) {
    int node = blockIdx.x * 8 + (threadIdx.x >> 5);
    int lane = threadIdx.x & 31;
    if (node >= NN) return;
    int e0 = g_rowptr[node], e1 = g_rowptr[node + 1];
    int deg = e1 - e0;
    float4 acc = make_float4(0.f, 0.f, 0.f, 0.f);
    if (deg > 0) {
        const float* qn = g_qx + node * RR;
        // pass 1: segment max
        float mv = -1e30f;
        for (int j = lane; j < deg; j += 32) {
            int se = g_srcet[e0 + j];
            float al = qn[se & 7] + g_kx[se];
            al = al >= 0.f ? al : 0.2f * al;
            mv = fmaxf(mv, al);
        }
#pragma unroll
        for (int o = 16; o > 0; o >>= 1) mv = fmaxf(mv, __shfl_xor_sync(~0u, mv, o));
        // pass 2: denom (kx/qx are L2-resident -> recompute is free)
        float ss = 0.f;
        for (int j = lane; j < deg; j += 32) {
            int se = g_srcet[e0 + j];
            float al = qn[se & 7] + g_kx[se];
            al = al >= 0.f ? al : 0.2f * al;
            ss += __expf(al - mv);
        }
#pragma unroll
        for (int o = 16; o > 0; o >>= 1) ss += __shfl_xor_sync(~0u, ss, o);
        float inv = 1.f / ss;
        // pass 3: weighted gather of xr rows (software-pipelined float4 gather)
        for (int jb = 0; jb < deg; jb += 32) {
            int j = jb + lane;
            int se = 0; float w = 0.f;
            if (j < deg) {
                se = g_srcet[e0 + j];
                float al = qn[se & 7] + g_kx[se];
                al = al >= 0.f ? al : 0.2f * al;
                w = __expf(al - mv) * inv;
            }
            int cnt = min(32, deg - jb);
            int st = __shfl_sync(~0u, se, 0);
            float4 v = ((const float4*)(g_xr + (size_t)st * HH))[lane];
            for (int t = 0; t < cnt; t++) {
                float wt = __shfl_sync(~0u, w, t);
                float4 cv = v;
                if (t + 1 < cnt) {
                    int sn = __shfl_sync(~0u, se, t + 1);
                    v = ((const float4*)(g_xr + (size_t)sn * HH))[lane];
                }
                acc.x += wt * cv.x; acc.y += wt * cv.y;
                acc.z += wt * cv.z; acc.w += wt * cv.w;
            }
        }
    }
    float4 bb = ((const float4*)bias)[lane];
    acc.x = fmaxf(acc.x + bb.x, 0.f);
    acc.y = fmaxf(acc.y + bb.y, 0.f);
    acc.z = fmaxf(acc.z + bb.z, 0.f);
    acc.w = fmaxf(acc.w + bb.w, 0.f);
    ((float4*)(hout + (size_t)node * HH))[lane] = acc;
}

// ---------------- final linear + log_softmax (fused, warp per node) ----------------
__global__ void __launch_bounds__(256) k_out(const float* __restrict__ h,
                                             const float* __restrict__ lw,
                                             const float* __restrict__ lb,
                                             float* __restrict__ out) {
    __shared__ float slw[HH * CC];
    for (int i = threadIdx.x; i < HH * CC; i += 256) slw[i] = lw[i];
    __syncthreads();
    int node = blockIdx.x * 8 + (threadIdx.x >> 5);
    int lane = threadIdx.x & 31;
    if (node >= NN) return;
    float4 hv = ((const float4*)(h + (size_t)node * HH))[lane];
    float l0 = lb[lane], l1 = lb[lane + 32];
#pragma unroll
    for (int g = 0; g < 32; g++) {
        float x0 = __shfl_sync(~0u, hv.x, g);
        float x1 = __shfl_sync(~0u, hv.y, g);
        float x2 = __shfl_sync(~0u, hv.z, g);
        float x3 = __shfl_sync(~0u, hv.w, g);
        const float* p = slw + (g * 4) * CC;
        l0 += x0 * p[lane];            l1 += x0 * p[lane + 32];
        l0 += x1 * p[CC + lane];       l1 += x1 * p[CC + lane + 32];
        l0 += x2 * p[2 * CC + lane];   l1 += x2 * p[2 * CC + lane + 32];
        l0 += x3 * p[3 * CC + lane];   l1 += x3 * p[3 * CC + lane + 32];
    }
    float m = fmaxf(l0, l1);
#pragma unroll
    for (int o = 16; o > 0; o >>= 1) m = fmaxf(m, __shfl_xor_sync(~0u, m, o));
    float s = __expf(l0 - m) + __expf(l1 - m);
#pragma unroll
    for (int o = 16; o > 0; o >>= 1) s += __shfl_xor_sync(~0u, s, o);
    float lse = m + logf(s);
    out[(size_t)node * CC + lane]      = l0 - lse;
    out[(size_t)node * CC + lane + 32] = l1 - lse;
}

// ---------------- launch ----------------
static void run_layer(const float* xin, const float* W, const float* q,
                      const float* k, const float* b, float* hout) {
    k_wqk<<<(RR * FF * 32) / 256, 256>>>(W, q, k);          // 1024 warps = 128 blocks
    k_qx<<<(NN + 7) / 8, 256>>>(xin);
    k_gemm<<<dim3((NN + 127) / 128, RR), 256>>>(xin, W);
    k_agg<<<(NN + 7) / 8, 256>>>(b, hout);
}

extern "C" void kernel_launch(void* const* d_in, const int* in_sizes, int n_in,
                              void* d_out, int out_size) {
    const float* x     = (const float*)d_in[0];
    const int*   ei    = (const int*)d_in[1];    // int32: JAX default x64-disabled
    const int*   et    = (const int*)d_in[2];
    const float* W1    = (const float*)d_in[3];
    const float* q1    = (const float*)d_in[4];
    const float* k1    = (const float*)d_in[5];
    const float* b1    = (const float*)d_in[6];
    const float* W2    = (const float*)d_in[7];
    const float* q2    = (const float*)d_in[8];
    const float* k2    = (const float*)d_in[9];
    const float* b2    = (const float*)d_in[10];
    const float* W3    = (const float*)d_in[11];
    const float* q3    = (const float*)d_in[12];
    const float* k3    = (const float*)d_in[13];
    const float* b3    = (const float*)d_in[14];
    const float* lin_w = (const float*)d_in[15];
    const float* lin_b = (const float*)d_in[16];

    float *h1, *h2;
    cudaGetSymbolAddress((void**)&h1, g_h1);
    cudaGetSymbolAddress((void**)&h2, g_h2);

    // CSR by dst (rebuilt every call; graph is an input)
    k_zero_deg<<<(NN + 255) / 256, 256>>>();
    k_count<<<(EE + 255) / 256, 256>>>(ei);
    k_scan<<<1, 1024>>>();
    k_fill<<<(EE + 255) / 256, 256>>>(ei, et);

    run_layer(x,  W1, q1, k1, b1, h1);
    run_layer(h1, W2, q2, k2, b2, h2);
    run_layer(h2, W3, q3, k3, b3, h1);

    k_out<<<(NN + 7) / 8, 256>>>(h1, lin_w, lin_b, (float*)d_out);
}

// round 4
// speedup vs baseline: 1.2817x; 1.2817x over previous
#include <cuda_runtime.h>
#include <cuda_bf16.h>
#include <cstdint>
#include <cstddef>

#define NN 50000
#define EE 800000
#define RR 8
#define FF 128
#define HH 128
#define CC 64
#define SCAN_B 49   // ceil(50000/1024)

// ---------------- static device scratch ----------------
__device__ __nv_bfloat16 g_xrb[(size_t)NN * RR * HH];   // bf16 messages
__device__ __nv_bfloat16 g_xb[(size_t)NN * HH];         // bf16 GEMM input (x or h)
__device__ __nv_bfloat16 g_wbt[(size_t)RR * HH * FF];   // W^T bf16 [r][n][f]
__device__ float g_h1[(size_t)NN * HH];
__device__ float g_h2[(size_t)NN * HH];
__device__ float g_qx[NN * RR];
__device__ float g_kx[NN * RR];
__device__ float g_wq[RR * FF];
__device__ float g_wk[RR * FF];
__device__ int   g_rowptr[NN + 1];
__device__ int   g_cursor[NN];
__device__ int   g_deg[NN];
__device__ int   g_part[64];
__device__ int   g_srcet[EE];   // src*8 + etype, grouped by dst

// ---------------- CSR build ----------------
__global__ void k_zero_deg() {
    int i = blockIdx.x * blockDim.x + threadIdx.x;
    if (i < NN) g_deg[i] = 0;
}

__global__ void k_count(const int* __restrict__ ei) {
    int e = blockIdx.x * blockDim.x + threadIdx.x;
    if (e < EE) atomicAdd(&g_deg[ei[EE + e]], 1);
}

// block-level inclusive scan (49 blocks x 1024)
__global__ void __launch_bounds__(1024) k_scan1() {
    int i = blockIdx.x * 1024 + threadIdx.x;
    int lane = threadIdx.x & 31, wid = threadIdx.x >> 5;
    int v = (i < NN) ? g_deg[i] : 0;
    int x = v;
#pragma unroll
    for (int o = 1; o < 32; o <<= 1) {
        int t = __shfl_up_sync(~0u, x, o);
        if (lane >= o) x += t;
    }
    __shared__ int wsum[32];
    if (lane == 31) wsum[wid] = x;
    __syncthreads();
    if (wid == 0) {
        int y = wsum[lane];
#pragma unroll
        for (int o = 1; o < 32; o <<= 1) {
            int t = __shfl_up_sync(~0u, y, o);
            if (lane >= o) y += t;
        }
        wsum[lane] = y;
    }
    __syncthreads();
    int incl = x + (wid > 0 ? wsum[wid - 1] : 0);
    if (i < NN) g_rowptr[i + 1] = incl;
    if (threadIdx.x == 1023) g_part[blockIdx.x] = incl;
}

__global__ void k_scan2() {
    if (threadIdx.x == 0) {
        int s = 0;
        for (int b = 0; b < SCAN_B; b++) { s += g_part[b]; g_part[b] = s; }
    }
}

__global__ void __launch_bounds__(1024) k_scan3() {
    int b = blockIdx.x;
    int i = b * 1024 + threadIdx.x;
    if (i < NN) {
        int off = (b > 0) ? g_part[b - 1] : 0;
        int rp = g_rowptr[i + 1] + off;
        g_rowptr[i + 1] = rp;
        g_cursor[i] = rp - g_deg[i];
    }
    if (i == 0) g_rowptr[0] = 0;
}

__global__ void k_fill(const int* __restrict__ ei, const int* __restrict__ et) {
    int e = blockIdx.x * blockDim.x + threadIdx.x;
    if (e < EE) {
        int d = ei[EE + e];
        int pos = atomicAdd(&g_cursor[d], 1);
        g_srcet[pos] = ei[e] * RR + et[e];
    }
}

// ---------------- conversions ----------------
__global__ void k_xconv(const float* __restrict__ x) {
    int i = blockIdx.x * blockDim.x + threadIdx.x;   // over N*H/2 float2s
    if (i < NN * HH / 2) {
        float2 v = ((const float2*)x)[i];
        ((__nv_bfloat162*)g_xb)[i] = __float22bfloat162_rn(v);
    }
}

// W[r][f][n] fp32 -> g_wbt[r][n][f] bf16 (smem transpose)
__global__ void k_wconv(const float* __restrict__ W) {
    __shared__ float t[32][33];
    int r = blockIdx.z, f0 = blockIdx.x * 32, n0 = blockIdx.y * 32;
    const float* Wr = W + (size_t)r * FF * HH;
    for (int i = threadIdx.y; i < 32; i += 8)
        t[i][threadIdx.x] = Wr[(size_t)(f0 + i) * HH + n0 + threadIdx.x];
    __syncthreads();
    __nv_bfloat16* out = g_wbt + ((size_t)r * HH + n0) * FF + f0;
    for (int i = threadIdx.y; i < 32; i += 8)
        out[(size_t)i * FF + threadIdx.x] = __float2bfloat16(t[threadIdx.x][i]);
}

// ---------------- wq[r,f] = W[r,f,:].q ;  wk[r,f] = W[r,f,:].k ----------------
__global__ void k_wqk(const float* __restrict__ W, const float* __restrict__ q,
                      const float* __restrict__ kk) {
    int warp = (blockIdx.x * blockDim.x + threadIdx.x) >> 5;
    int lane = threadIdx.x & 31;
    if (warp >= RR * FF) return;
    const float* wrow = W + (size_t)warp * HH;
    float sq = 0.f, sk = 0.f;
#pragma unroll
    for (int i = 0; i < 4; i++) {
        int h = lane + 32 * i;
        float wv = wrow[h];
        sq += wv * q[h];
        sk += wv * kk[h];
    }
#pragma unroll
    for (int o = 16; o > 0; o >>= 1) {
        sq += __shfl_xor_sync(~0u, sq, o);
        sk += __shfl_xor_sync(~0u, sk, o);
    }
    if (lane == 0) { g_wq[warp] = sq; g_wk[warp] = sk; }
}

// ---------------- qx[n,r] = x[n,:].wq[r,:] (exact fp32 scores) ----------------
__global__ void __launch_bounds__(256) k_qx(const float* __restrict__ x) {
    __shared__ float swq[RR * FF];
    __shared__ float swk[RR * FF];
    for (int i = threadIdx.x; i < RR * FF; i += 256) { swq[i] = g_wq[i]; swk[i] = g_wk[i]; }
    __syncthreads();
    int node = blockIdx.x * 8 + (threadIdx.x >> 5);
    int lane = threadIdx.x & 31;
    if (node >= NN) return;
    float4 xv = ((const float4*)(x + (size_t)node * FF))[lane];
#pragma unroll
    for (int r = 0; r < RR; r++) {
        float4 a = ((const float4*)(swq + r * FF))[lane];
        float4 b = ((const float4*)(swk + r * FF))[lane];
        float sq = xv.x * a.x + xv.y * a.y + xv.z * a.z + xv.w * a.w;
        float sk = xv.x * b.x + xv.y * b.y + xv.z * b.z + xv.w * b.w;
#pragma unroll
        for (int o = 16; o > 0; o >>= 1) {
            sq += __shfl_xor_sync(~0u, sq, o);
            sk += __shfl_xor_sync(~0u, sk, o);
        }
        if (lane == 0) { g_qx[node * RR + r] = sq; g_kx[node * RR + r] = sk; }
    }
}

// ---------------- batched GEMM: xr[n, r, :] = x[n,:] @ W[r]  (bf16 m16n8k16) ----------------
__device__ __forceinline__ unsigned packbf(float a, float b) {
    __nv_bfloat162 h = __float22bfloat162_rn(make_float2(a, b));
    return *(unsigned*)&h;
}

__global__ void __launch_bounds__(256, 2) k_gemm() {
    __shared__ unsigned sA[128][36];   // [m][k-pair] bf16x2
    __shared__ unsigned sB[128][36];   // [n][k-pair] bf16x2
    int r  = blockIdx.y;
    int m0 = blockIdx.x * 128;
    int tid = threadIdx.x;
    int lane = tid & 31, warp = tid >> 5;
    int wm = warp & 3, wn = warp >> 2;   // 4 m-subtiles x 2 n-subtiles
    int q4 = lane & 3, g8 = lane >> 2;

    const unsigned* xb = (const unsigned*)g_xb;                        // [N][64]
    const unsigned* wb = (const unsigned*)g_wbt + (size_t)r * 128 * 64; // [n][64]

    float acc[2][8][4];
#pragma unroll
    for (int i = 0; i < 2; i++)
#pragma unroll
        for (int j = 0; j < 8; j++)
#pragma unroll
            for (int c = 0; c < 4; c++) acc[i][j][c] = 0.f;

    for (int kc = 0; kc < 2; kc++) {
#pragma unroll
        for (int i = 0; i < 4; i++) {
            int id = tid + i * 256;              // 1024 uint4 per operand
            int row = id >> 3, c4 = id & 7;
            int rowc = min(m0 + row, NN - 1);
            uint4 va = ((const uint4*)(xb + (size_t)rowc * 64 + kc * 32))[c4];
            *(uint4*)&sA[row][c4 * 4] = va;
            uint4 vb = ((const uint4*)(wb + (size_t)row * 64 + kc * 32))[c4];
            *(uint4*)&sB[row][c4 * 4] = vb;
        }
        __syncthreads();
#pragma unroll
        for (int k = 0; k < 4; k++) {            // 4 k16-steps per 64-K half
            int kb = k * 8;
            unsigned a[2][4];
#pragma unroll
            for (int mt = 0; mt < 2; mt++) {
                int r0 = wm * 32 + mt * 16 + g8;
                a[mt][0] = sA[r0][kb + q4];
                a[mt][1] = sA[r0 + 8][kb + q4];
                a[mt][2] = sA[r0][kb + q4 + 4];
                a[mt][3] = sA[r0 + 8][kb + q4 + 4];
            }
#pragma unroll
            for (int nt = 0; nt < 8; nt++) {
                int nc = wn * 64 + nt * 8 + g8;
                unsigned b0 = sB[nc][kb + q4];
                unsigned b1 = sB[nc][kb + q4 + 4];
#pragma unroll
                for (int mt = 0; mt < 2; mt++) {
                    asm volatile(
                        "mma.sync.aligned.m16n8k16.row.col.f32.bf16.bf16.f32 "
                        "{%0,%1,%2,%3}, {%4,%5,%6,%7}, {%8,%9}, {%0,%1,%2,%3};"
                        : "+f"(acc[mt][nt][0]), "+f"(acc[mt][nt][1]),
                          "+f"(acc[mt][nt][2]), "+f"(acc[mt][nt][3])
                        : "r"(a[mt][0]), "r"(a[mt][1]), "r"(a[mt][2]), "r"(a[mt][3]),
                          "r"(b0), "r"(b1));
                }
            }
        }
        __syncthreads();
    }

    // epilogue through smem -> coalesced bf16 row writes
    unsigned (*sC)[68] = (unsigned(*)[68])&sA[0][0];   // 128*68 <= 2*128*36 uints
#pragma unroll
    for (int mt = 0; mt < 2; mt++) {
        int row = wm * 32 + mt * 16 + g8;
#pragma unroll
        for (int nt = 0; nt < 8; nt++) {
            int cp = wn * 32 + nt * 4 + q4;
            sC[row][cp]     = packbf(acc[mt][nt][0], acc[mt][nt][1]);
            sC[row + 8][cp] = packbf(acc[mt][nt][2], acc[mt][nt][3]);
        }
    }
    __syncthreads();
    unsigned* xr = (unsigned*)g_xrb;
    int row = tid >> 1, half = tid & 1;
    int gm = m0 + row;
    if (gm < NN) {
        size_t dst = ((size_t)gm * RR + r) * 64 + half * 32;
#pragma unroll
        for (int j = 0; j < 8; j++) {
            uint4 v = *(uint4*)&sC[row][half * 32 + j * 4];
            *(uint4*)(xr + dst + j * 4) = v;
        }
    }
}

// ------- fused per-node: scores -> segment softmax -> pipelined bf16 gather -> +b, relu -------
__device__ __forceinline__ float bflo(unsigned u) { return __uint_as_float(u << 16); }
__device__ __forceinline__ float bfhi(unsigned u) { return __uint_as_float(u & 0xffff0000u); }

__global__ void __launch_bounds__(256) k_agg(const float* __restrict__ bias,
                                             float* __restrict__ hout) {
    int node = blockIdx.x * 8 + (threadIdx.x >> 5);
    int lane = threadIdx.x & 31;
    if (node >= NN) return;
    int e0 = g_rowptr[node], e1 = g_rowptr[node + 1];
    int deg = e1 - e0;
    float4 acc = make_float4(0.f, 0.f, 0.f, 0.f);
    if (deg > 0) {
        const float* qn = g_qx + node * RR;
        float mv = -1e30f;
        for (int j = lane; j < deg; j += 32) {
            int se = g_srcet[e0 + j];
            float al = qn[se & 7] + g_kx[se];
            al = al >= 0.f ? al : 0.2f * al;
            mv = fmaxf(mv, al);
        }
#pragma unroll
        for (int o = 16; o > 0; o >>= 1) mv = fmaxf(mv, __shfl_xor_sync(~0u, mv, o));
        float ss = 0.f;
        for (int j = lane; j < deg; j += 32) {
            int se = g_srcet[e0 + j];
            float al = qn[se & 7] + g_kx[se];
            al = al >= 0.f ? al : 0.2f * al;
            ss += __expf(al - mv);
        }
#pragma unroll
        for (int o = 16; o > 0; o >>= 1) ss += __shfl_xor_sync(~0u, ss, o);
        float inv = 1.f / ss;

        const uint2* xr2 = (const uint2*)g_xrb;   // row = 32 uint2 (128 bf16)
        for (int jb = 0; jb < deg; jb += 32) {
            int j = jb + lane;
            int se = 0; float w = 0.f;
            if (j < deg) {
                se = g_srcet[e0 + j];
                float al = qn[se & 7] + g_kx[se];
                al = al >= 0.f ? al : 0.2f * al;
                w = __expf(al - mv) * inv;
            }
            int cnt = min(32, deg - jb);
            uint2 va[4];
#pragma unroll
            for (int g = 0; g < 4; g++) {
                int s = __shfl_sync(~0u, se, g);
                if (g < cnt) va[g] = xr2[(size_t)s * 32 + lane];
            }
            for (int t0 = 0; t0 < cnt; t0 += 4) {
                uint2 vb[4];
#pragma unroll
                for (int g = 0; g < 4; g++) {
                    int idx = t0 + 4 + g;
                    int s = __shfl_sync(~0u, se, idx & 31);
                    if (idx < cnt) vb[g] = xr2[(size_t)s * 32 + lane];
                }
#pragma unroll
                for (int g = 0; g < 4; g++) {
                    int idx = t0 + g;
                    if (idx < cnt) {
                        float wt = __shfl_sync(~0u, w, idx);
                        acc.x += wt * bflo(va[g].x);
                        acc.y += wt * bfhi(va[g].x);
                        acc.z += wt * bflo(va[g].y);
                        acc.w += wt * bfhi(va[g].y);
                    }
                }
                va[0] = vb[0]; va[1] = vb[1]; va[2] = vb[2]; va[3] = vb[3];
            }
        }
    }
    float4 bb = ((const float4*)bias)[lane];
    acc.x = fmaxf(acc.x + bb.x, 0.f);
    acc.y = fmaxf(acc.y + bb.y, 0.f);
    acc.z = fmaxf(acc.z + bb.z, 0.f);
    acc.w = fmaxf(acc.w + bb.w, 0.f);
    ((float4*)(hout + (size_t)node * HH))[lane] = acc;
    // bf16 copy for next layer's GEMM input
    uint2 hb;
    hb.x = packbf(acc.x, acc.y);
    hb.y = packbf(acc.z, acc.w);
    ((uint2*)(g_xb + (size_t)node * HH))[lane] = hb;
}

// ---------------- final linear + log_softmax ----------------
__global__ void __launch_bounds__(256) k_out(const float* __restrict__ h,
                                             const float* __restrict__ lw,
                                             const float* __restrict__ lb,
                                             float* __restrict__ out) {
    __shared__ float slw[HH * CC];
    for (int i = threadIdx.x; i < HH * CC; i += 256) slw[i] = lw[i];
    __syncthreads();
    int node = blockIdx.x * 8 + (threadIdx.x >> 5);
    int lane = threadIdx.x & 31;
    if (node >= NN) return;
    float4 hv = ((const float4*)(h + (size_t)node * HH))[lane];
    float l0 = lb[lane], l1 = lb[lane + 32];
#pragma unroll
    for (int g = 0; g < 32; g++) {
        float x0 = __shfl_sync(~0u, hv.x, g);
        float x1 = __shfl_sync(~0u, hv.y, g);
        float x2 = __shfl_sync(~0u, hv.z, g);
        float x3 = __shfl_sync(~0u, hv.w, g);
        const float* p = slw + (g * 4) * CC;
        l0 += x0 * p[lane];            l1 += x0 * p[lane + 32];
        l0 += x1 * p[CC + lane];       l1 += x1 * p[CC + lane + 32];
        l0 += x2 * p[2 * CC + lane];   l1 += x2 * p[2 * CC + lane + 32];
        l0 += x3 * p[3 * CC + lane];   l1 += x3 * p[3 * CC + lane + 32];
    }
    float m = fmaxf(l0, l1);
#pragma unroll
    for (int o = 16; o > 0; o >>= 1) m = fmaxf(m, __shfl_xor_sync(~0u, m, o));
    float s = __expf(l0 - m) + __expf(l1 - m);
#pragma unroll
    for (int o = 16; o > 0; o >>= 1) s += __shfl_xor_sync(~0u, s, o);
    float lse = m + logf(s);
    out[(size_t)node * CC + lane]      = l0 - lse;
    out[(size_t)node * CC + lane + 32] = l1 - lse;
}

// ---------------- launch ----------------
extern "C" void kernel_launch(void* const* d_in, const int* in_sizes, int n_in,
                              void* d_out, int out_size) {
    const float* x     = (const float*)d_in[0];
    const int*   ei    = (const int*)d_in[1];   // int32 (JAX x64 disabled)
    const int*   et    = (const int*)d_in[2];
    const float* W1    = (const float*)d_in[3];
    const float* q1    = (const float*)d_in[4];
    const float* k1    = (const float*)d_in[5];
    const float* b1    = (const float*)d_in[6];
    const float* W2    = (const float*)d_in[7];
    const float* q2    = (const float*)d_in[8];
    const float* k2    = (const float*)d_in[9];
    const float* b2    = (const float*)d_in[10];
    const float* W3    = (const float*)d_in[11];
    const float* q3    = (const float*)d_in[12];
    const float* k3    = (const float*)d_in[13];
    const float* b3    = (const float*)d_in[14];
    const float* lin_w = (const float*)d_in[15];
    const float* lin_b = (const float*)d_in[16];

    float *h1, *h2;
    cudaGetSymbolAddress((void**)&h1, g_h1);
    cudaGetSymbolAddress((void**)&h2, g_h2);

    dim3 wc_grid(4, 4, 8), wc_blk(32, 8);
    dim3 gemm_grid((NN + 127) / 128, RR);

    // ---- layer 1 front half ordered so capture slot #5 == k_gemm (layer 1) ----
    k_xconv<<<(NN * HH / 2 + 255) / 256, 256>>>(x);            // 0
    k_wconv<<<wc_grid, wc_blk>>>(W1);                          // 1
    k_zero_deg<<<(NN + 255) / 256, 256>>>();                   // 2
    k_count<<<(EE + 255) / 256, 256>>>(ei);                    // 3
    k_scan1<<<SCAN_B, 1024>>>();                               // 4
    k_gemm<<<gemm_grid, 256>>>();                              // 5  <- profiled
    k_scan2<<<1, 64>>>();                                      // 6
    k_scan3<<<SCAN_B, 1024>>>();                               // 7
    k_fill<<<(EE + 255) / 256, 256>>>(ei, et);                 // 8
    k_wqk<<<(RR * FF * 32) / 256, 256>>>(W1, q1, k1);          // 9
    k_qx<<<(NN + 7) / 8, 256>>>(x);                            // 10
    k_agg<<<(NN + 7) / 8, 256>>>(b1, h1);                      // 11

    // ---- layer 2 ----
    k_wconv<<<wc_grid, wc_blk>>>(W2);
    k_wqk<<<(RR * FF * 32) / 256, 256>>>(W2, q2, k2);
    k_qx<<<(NN + 7) / 8, 256>>>(h1);
    k_gemm<<<gemm_grid, 256>>>();
    k_agg<<<(NN + 7) / 8, 256>>>(b2, h2);

    // ---- layer 3 ----
    k_wconv<<<wc_grid, wc_blk>>>(W3);
    k_wqk<<<(RR * FF * 32) / 256, 256>>>(W3, q3, k3);
    k_qx<<<(NN + 7) / 8, 256>>>(h2);
    k_gemm<<<gemm_grid, 256>>>();
    k_agg<<<(NN + 7) / 8, 256>>>(b3, h1);

    k_out<<<(NN + 7) / 8, 256>>>(h1, lin_w, lin_b, (float*)d_out);
}

// round 5
// speedup vs baseline: 1.3763x; 1.0738x over previous
#include <cuda_runtime.h>
#include <cuda_bf16.h>
#include <cstdint>
#include <cstddef>

#define NN 50000
#define EE 800000
#define RR 8
#define FF 128
#define HH 128
#define CC 64
#define SCAN_B 49   // ceil(50000/1024)

// ---------------- static device scratch ----------------
__device__ __nv_bfloat16 g_xrb[(size_t)NN * RR * HH];   // bf16 messages
__device__ __nv_bfloat16 g_xb[(size_t)NN * HH];         // bf16 GEMM input (x or h)
__device__ __nv_bfloat16 g_wbt[(size_t)RR * HH * FF];   // W^T bf16 [r][n][f]
__device__ float g_h1[(size_t)NN * HH];
__device__ float g_h2[(size_t)NN * HH];
__device__ float g_qx[NN * RR];
__device__ float g_kx[NN * RR];
__device__ float g_wq[RR * FF];
__device__ float g_wk[RR * FF];
__device__ int   g_rowptr[NN + 1];
__device__ int   g_cursor[NN];
__device__ int   g_deg[NN];
__device__ int   g_part[64];
__device__ int   g_srcet[EE];   // src*8 + etype, grouped by dst

// ---------------- CSR build ----------------
__global__ void k_zero_deg() {
    int i = blockIdx.x * blockDim.x + threadIdx.x;
    if (i < NN) g_deg[i] = 0;
}

__global__ void k_count(const int* __restrict__ ei) {
    int e = blockIdx.x * blockDim.x + threadIdx.x;
    if (e < EE) atomicAdd(&g_deg[ei[EE + e]], 1);
}

__global__ void __launch_bounds__(1024) k_scan1() {
    int i = blockIdx.x * 1024 + threadIdx.x;
    int lane = threadIdx.x & 31, wid = threadIdx.x >> 5;
    int v = (i < NN) ? g_deg[i] : 0;
    int x = v;
#pragma unroll
    for (int o = 1; o < 32; o <<= 1) {
        int t = __shfl_up_sync(~0u, x, o);
        if (lane >= o) x += t;
    }
    __shared__ int wsum[32];
    if (lane == 31) wsum[wid] = x;
    __syncthreads();
    if (wid == 0) {
        int y = wsum[lane];
#pragma unroll
        for (int o = 1; o < 32; o <<= 1) {
            int t = __shfl_up_sync(~0u, y, o);
            if (lane >= o) y += t;
        }
        wsum[lane] = y;
    }
    __syncthreads();
    int incl = x + (wid > 0 ? wsum[wid - 1] : 0);
    if (i < NN) g_rowptr[i + 1] = incl;
    if (threadIdx.x == 1023) g_part[blockIdx.x] = incl;
}

__global__ void k_scan2() {
    if (threadIdx.x == 0) {
        int s = 0;
        for (int b = 0; b < SCAN_B; b++) { s += g_part[b]; g_part[b] = s; }
    }
}

__global__ void __launch_bounds__(1024) k_scan3() {
    int b = blockIdx.x;
    int i = b * 1024 + threadIdx.x;
    if (i < NN) {
        int off = (b > 0) ? g_part[b - 1] : 0;
        int rp = g_rowptr[i + 1] + off;
        g_rowptr[i + 1] = rp;
        g_cursor[i] = rp - g_deg[i];
    }
    if (i == 0) g_rowptr[0] = 0;
}

__global__ void k_fill(const int* __restrict__ ei, const int* __restrict__ et) {
    int e = blockIdx.x * blockDim.x + threadIdx.x;
    if (e < EE) {
        int d = ei[EE + e];
        int pos = atomicAdd(&g_cursor[d], 1);
        g_srcet[pos] = ei[e] * RR + et[e];
    }
}

// ---------------- conversions ----------------
__global__ void k_xconv(const float* __restrict__ x) {
    int i = blockIdx.x * blockDim.x + threadIdx.x;
    if (i < NN * HH / 2) {
        float2 v = ((const float2*)x)[i];
        ((__nv_bfloat162*)g_xb)[i] = __float22bfloat162_rn(v);
    }
}

// W[r][f][n] fp32 -> g_wbt[r][n][f] bf16 (smem transpose)
__global__ void k_wconv(const float* __restrict__ W) {
    __shared__ float t[32][33];
    int r = blockIdx.z, f0 = blockIdx.x * 32, n0 = blockIdx.y * 32;
    const float* Wr = W + (size_t)r * FF * HH;
    for (int i = threadIdx.y; i < 32; i += 8)
        t[i][threadIdx.x] = Wr[(size_t)(f0 + i) * HH + n0 + threadIdx.x];
    __syncthreads();
    __nv_bfloat16* out = g_wbt + ((size_t)r * HH + n0) * FF + f0;
    for (int i = threadIdx.y; i < 32; i += 8)
        out[(size_t)i * FF + threadIdx.x] = __float2bfloat16(t[threadIdx.x][i]);
}

// ---------------- wq[r,f] = W[r,f,:].q ;  wk[r,f] = W[r,f,:].k ----------------
__global__ void k_wqk(const float* __restrict__ W, const float* __restrict__ q,
                      const float* __restrict__ kk) {
    int warp = (blockIdx.x * blockDim.x + threadIdx.x) >> 5;
    int lane = threadIdx.x & 31;
    if (warp >= RR * FF) return;
    const float* wrow = W + (size_t)warp * HH;
    float sq = 0.f, sk = 0.f;
#pragma unroll
    for (int i = 0; i < 4; i++) {
        int h = lane + 32 * i;
        float wv = wrow[h];
        sq += wv * q[h];
        sk += wv * kk[h];
    }
#pragma unroll
    for (int o = 16; o > 0; o >>= 1) {
        sq += __shfl_xor_sync(~0u, sq, o);
        sk += __shfl_xor_sync(~0u, sk, o);
    }
    if (lane == 0) { g_wq[warp] = sq; g_wk[warp] = sk; }
}

// ---------------- qx[n,r] = x[n,:].wq[r,:] (exact fp32 scores) ----------------
__global__ void __launch_bounds__(256) k_qx(const float* __restrict__ x) {
    __shared__ float swq[RR * FF];
    __shared__ float swk[RR * FF];
    for (int i = threadIdx.x; i < RR * FF; i += 256) { swq[i] = g_wq[i]; swk[i] = g_wk[i]; }
    __syncthreads();
    int node = blockIdx.x * 8 + (threadIdx.x >> 5);
    int lane = threadIdx.x & 31;
    if (node >= NN) return;
    float4 xv = ((const float4*)(x + (size_t)node * FF))[lane];
#pragma unroll
    for (int r = 0; r < RR; r++) {
        float4 a = ((const float4*)(swq + r * FF))[lane];
        float4 b = ((const float4*)(swk + r * FF))[lane];
        float sq = xv.x * a.x + xv.y * a.y + xv.z * a.z + xv.w * a.w;
        float sk = xv.x * b.x + xv.y * b.y + xv.z * b.z + xv.w * b.w;
#pragma unroll
        for (int o = 16; o > 0; o >>= 1) {
            sq += __shfl_xor_sync(~0u, sq, o);
            sk += __shfl_xor_sync(~0u, sk, o);
        }
        if (lane == 0) { g_qx[node * RR + r] = sq; g_kx[node * RR + r] = sk; }
    }
}

// ---------------- batched GEMM: xr[n,r,:] = x[n,:] @ W[r]  (bf16 m16n8k16 + ldmatrix) ----------------
__device__ __forceinline__ unsigned packbf(float a, float b) {
    __nv_bfloat162 h = __float22bfloat162_rn(make_float2(a, b));
    return *(unsigned*)&h;
}

__device__ __forceinline__ unsigned sptr(const void* p) {
    return (unsigned)__cvta_generic_to_shared(p);
}

__device__ __forceinline__ void ldsm4(unsigned& r0, unsigned& r1, unsigned& r2,
                                      unsigned& r3, unsigned addr) {
    asm volatile("ldmatrix.sync.aligned.m8n8.x4.shared.b16 {%0,%1,%2,%3}, [%4];"
                 : "=r"(r0), "=r"(r1), "=r"(r2), "=r"(r3) : "r"(addr));
}

__global__ void __launch_bounds__(256, 2) k_gemm() {
    __shared__ unsigned sbuf[2][128][36];   // [0]=A (m x kpair), [1]=B (n x kpair)
    int r  = blockIdx.y;
    int m0 = blockIdx.x * 128;
    int tid = threadIdx.x;
    int lane = tid & 31, warp = tid >> 5;
    int wm = warp & 3, wn = warp >> 2;
    int l7 = lane & 7, lt = lane >> 3;

    const unsigned* xb = (const unsigned*)g_xb;                         // [N][64]
    const unsigned* wb = (const unsigned*)g_wbt + (size_t)r * 128 * 64; // [n][64]

    float acc[2][8][4];
#pragma unroll
    for (int i = 0; i < 2; i++)
#pragma unroll
        for (int j = 0; j < 8; j++)
#pragma unroll
            for (int c = 0; c < 4; c++) acc[i][j][c] = 0.f;

    for (int kc = 0; kc < 2; kc++) {
#pragma unroll
        for (int i = 0; i < 4; i++) {
            int id = tid + i * 256;
            int row = id >> 3, c4 = id & 7;
            int rowc = min(m0 + row, NN - 1);
            uint4 va = ((const uint4*)(xb + (size_t)rowc * 64 + kc * 32))[c4];
            *(uint4*)&sbuf[0][row][c4 * 4] = va;
            uint4 vb = ((const uint4*)(wb + (size_t)row * 64 + kc * 32))[c4];
            *(uint4*)&sbuf[1][row][c4 * 4] = vb;
        }
        __syncthreads();
#pragma unroll
        for (int k = 0; k < 4; k++) {
            int kb = k * 8;
            int kcol = kb + (lt >> 1) * 4;
            int rsub = (lt & 1) * 8 + l7;
            unsigned a[2][4];
#pragma unroll
            for (int mt = 0; mt < 2; mt++) {
                unsigned addr = sptr(&sbuf[0][wm * 32 + mt * 16 + rsub][kcol]);
                ldsm4(a[mt][0], a[mt][1], a[mt][2], a[mt][3], addr);
            }
#pragma unroll
            for (int ntp = 0; ntp < 4; ntp++) {
                unsigned b0e, b0o, b1e, b1o;
                unsigned addr = sptr(&sbuf[1][wn * 64 + ntp * 16 + rsub][kcol]);
                ldsm4(b0e, b0o, b1e, b1o, addr);
#pragma unroll
                for (int mt = 0; mt < 2; mt++) {
                    asm volatile(
                        "mma.sync.aligned.m16n8k16.row.col.f32.bf16.bf16.f32 "
                        "{%0,%1,%2,%3}, {%4,%5,%6,%7}, {%8,%9}, {%0,%1,%2,%3};"
                        : "+f"(acc[mt][ntp * 2][0]), "+f"(acc[mt][ntp * 2][1]),
                          "+f"(acc[mt][ntp * 2][2]), "+f"(acc[mt][ntp * 2][3])
                        : "r"(a[mt][0]), "r"(a[mt][1]), "r"(a[mt][2]), "r"(a[mt][3]),
                          "r"(b0e), "r"(b1e));
                    asm volatile(
                        "mma.sync.aligned.m16n8k16.row.col.f32.bf16.bf16.f32 "
                        "{%0,%1,%2,%3}, {%4,%5,%6,%7}, {%8,%9}, {%0,%1,%2,%3};"
                        : "+f"(acc[mt][ntp * 2 + 1][0]), "+f"(acc[mt][ntp * 2 + 1][1]),
                          "+f"(acc[mt][ntp * 2 + 1][2]), "+f"(acc[mt][ntp * 2 + 1][3])
                        : "r"(a[mt][0]), "r"(a[mt][1]), "r"(a[mt][2]), "r"(a[mt][3]),
                          "r"(b0o), "r"(b1o));
                }
            }
        }
        __syncthreads();
    }

    // epilogue through smem -> coalesced bf16 row writes (sbuf reused: 128x68 <= 2*128*36)
    int q4 = lane & 3, g8 = lane >> 2;
    unsigned (*sC)[68] = (unsigned(*)[68])&sbuf[0][0][0];
#pragma unroll
    for (int mt = 0; mt < 2; mt++) {
        int row = wm * 32 + mt * 16 + g8;
#pragma unroll
        for (int nt = 0; nt < 8; nt++) {
            int cp = wn * 32 + nt * 4 + q4;
            sC[row][cp]     = packbf(acc[mt][nt][0], acc[mt][nt][1]);
            sC[row + 8][cp] = packbf(acc[mt][nt][2], acc[mt][nt][3]);
        }
    }
    __syncthreads();
    unsigned* xr = (unsigned*)g_xrb;
    int row = tid >> 1, half = tid & 1;
    int gm = m0 + row;
    if (gm < NN) {
        size_t dst = ((size_t)gm * RR + r) * 64 + half * 32;
#pragma unroll
        for (int j = 0; j < 8; j++) {
            uint4 v = *(uint4*)&sC[row][half * 32 + j * 4];
            *(uint4*)(xr + dst + j * 4) = v;
        }
    }
}

// ------- fused per-node: scores -> segment softmax -> pipelined bf16 gather -> +b, relu -------
__device__ __forceinline__ float bflo(unsigned u) { return __uint_as_float(u << 16); }
__device__ __forceinline__ float bfhi(unsigned u) { return __uint_as_float(u & 0xffff0000u); }

__global__ void __launch_bounds__(256) k_agg(const float* __restrict__ bias,
                                             float* __restrict__ hout) {
    int node = blockIdx.x * 8 + (threadIdx.x >> 5);
    int lane = threadIdx.x & 31;
    if (node >= NN) return;
    int e0 = g_rowptr[node], e1 = g_rowptr[node + 1];
    int deg = e1 - e0;
    float4 acc = make_float4(0.f, 0.f, 0.f, 0.f);
    const uint2* xr2 = (const uint2*)g_xrb;   // row = 32 uint2 (128 bf16)

    if (deg > 0 && deg <= 32) {
        // ---- fast path: one edge per lane, single load + single exp round ----
        const float* qn = g_qx + node * RR;
        int se = 0;
        float al = -1e30f;
        if (lane < deg) {
            se = g_srcet[e0 + lane];
            al = qn[se & 7] + g_kx[se];
            al = al >= 0.f ? al : 0.2f * al;
        }
        float mv = al;
#pragma unroll
        for (int o = 16; o > 0; o >>= 1) mv = fmaxf(mv, __shfl_xor_sync(~0u, mv, o));
        float ex = (lane < deg) ? __expf(al - mv) : 0.f;
        float ss = ex;
#pragma unroll
        for (int o = 16; o > 0; o >>= 1) ss += __shfl_xor_sync(~0u, ss, o);
        float w = ex / ss;

        uint2 va[4];
#pragma unroll
        for (int g = 0; g < 4; g++) {
            int s = __shfl_sync(~0u, se, g);
            if (g < deg) va[g] = xr2[(size_t)s * 32 + lane];
        }
        for (int t0 = 0; t0 < deg; t0 += 4) {
            uint2 vb[4];
#pragma unroll
            for (int g = 0; g < 4; g++) {
                int idx = t0 + 4 + g;
                int s = __shfl_sync(~0u, se, idx & 31);
                if (idx < deg) vb[g] = xr2[(size_t)s * 32 + lane];
            }
#pragma unroll
            for (int g = 0; g < 4; g++) {
                int idx = t0 + g;
                if (idx < deg) {
                    float wt = __shfl_sync(~0u, w, idx);
                    acc.x += wt * bflo(va[g].x);
                    acc.y += wt * bfhi(va[g].x);
                    acc.z += wt * bflo(va[g].y);
                    acc.w += wt * bfhi(va[g].y);
                }
            }
            va[0] = vb[0]; va[1] = vb[1]; va[2] = vb[2]; va[3] = vb[3];
        }
    } else if (deg > 32) {
        // ---- general path ----
        const float* qn = g_qx + node * RR;
        float mv = -1e30f;
        for (int j = lane; j < deg; j += 32) {
            int se = g_srcet[e0 + j];
            float al = qn[se & 7] + g_kx[se];
            al = al >= 0.f ? al : 0.2f * al;
            mv = fmaxf(mv, al);
        }
#pragma unroll
        for (int o = 16; o > 0; o >>= 1) mv = fmaxf(mv, __shfl_xor_sync(~0u, mv, o));
        float ss = 0.f;
        for (int j = lane; j < deg; j += 32) {
            int se = g_srcet[e0 + j];
            float al = qn[se & 7] + g_kx[se];
            al = al >= 0.f ? al : 0.2f * al;
            ss += __expf(al - mv);
        }
#pragma unroll
        for (int o = 16; o > 0; o >>= 1) ss += __shfl_xor_sync(~0u, ss, o);
        float inv = 1.f / ss;

        for (int jb = 0; jb < deg; jb += 32) {
            int j = jb + lane;
            int se = 0; float w = 0.f;
            if (j < deg) {
                se = g_srcet[e0 + j];
                float al = qn[se & 7] + g_kx[se];
                al = al >= 0.f ? al : 0.2f * al;
                w = __expf(al - mv) * inv;
            }
            int cnt = min(32, deg - jb);
            uint2 va[4];
#pragma unroll
            for (int g = 0; g < 4; g++) {
                int s = __shfl_sync(~0u, se, g);
                if (g < cnt) va[g] = xr2[(size_t)s * 32 + lane];
            }
            for (int t0 = 0; t0 < cnt; t0 += 4) {
                uint2 vb[4];
#pragma unroll
                for (int g = 0; g < 4; g++) {
                    int idx = t0 + 4 + g;
                    int s = __shfl_sync(~0u, se, idx & 31);
                    if (idx < cnt) vb[g] = xr2[(size_t)s * 32 + lane];
                }
#pragma unroll
                for (int g = 0; g < 4; g++) {
                    int idx = t0 + g;
                    if (idx < cnt) {
                        float wt = __shfl_sync(~0u, w, idx);
                        acc.x += wt * bflo(va[g].x);
                        acc.y += wt * bfhi(va[g].x);
                        acc.z += wt * bflo(va[g].y);
                        acc.w += wt * bfhi(va[g].y);
                    }
                }
                va[0] = vb[0]; va[1] = vb[1]; va[2] = vb[2]; va[3] = vb[3];
            }
        }
    }
    float4 bb = ((const float4*)bias)[lane];
    acc.x = fmaxf(acc.x + bb.x, 0.f);
    acc.y = fmaxf(acc.y + bb.y, 0.f);
    acc.z = fmaxf(acc.z + bb.z, 0.f);
    acc.w = fmaxf(acc.w + bb.w, 0.f);
    ((float4*)(hout + (size_t)node * HH))[lane] = acc;
    uint2 hb;
    hb.x = packbf(acc.x, acc.y);
    hb.y = packbf(acc.z, acc.w);
    ((uint2*)(g_xb + (size_t)node * HH))[lane] = hb;
}

// ---------------- final linear + log_softmax ----------------
__global__ void __launch_bounds__(256) k_out(const float* __restrict__ h,
                                             const float* __restrict__ lw,
                                             const float* __restrict__ lb,
                                             float* __restrict__ out) {
    __shared__ float slw[HH * CC];
    for (int i = threadIdx.x; i < HH * CC; i += 256) slw[i] = lw[i];
    __syncthreads();
    int node = blockIdx.x * 8 + (threadIdx.x >> 5);
    int lane = threadIdx.x & 31;
    if (node >= NN) return;
    float4 hv = ((const float4*)(h + (size_t)node * HH))[lane];
    float l0 = lb[lane], l1 = lb[lane + 32];
#pragma unroll
    for (int g = 0; g < 32; g++) {
        float x0 = __shfl_sync(~0u, hv.x, g);
        float x1 = __shfl_sync(~0u, hv.y, g);
        float x2 = __shfl_sync(~0u, hv.z, g);
        float x3 = __shfl_sync(~0u, hv.w, g);
        const float* p = slw + (g * 4) * CC;
        l0 += x0 * p[lane];            l1 += x0 * p[lane + 32];
        l0 += x1 * p[CC + lane];       l1 += x1 * p[CC + lane + 32];
        l0 += x2 * p[2 * CC + lane];   l1 += x2 * p[2 * CC + lane + 32];
        l0 += x3 * p[3 * CC + lane];   l1 += x3 * p[3 * CC + lane + 32];
    }
    float m = fmaxf(l0, l1);
#pragma unroll
    for (int o = 16; o > 0; o >>= 1) m = fmaxf(m, __shfl_xor_sync(~0u, m, o));
    float s = __expf(l0 - m) + __expf(l1 - m);
#pragma unroll
    for (int o = 16; o > 0; o >>= 1) s += __shfl_xor_sync(~0u, s, o);
    float lse = m + logf(s);
    out[(size_t)node * CC + lane]      = l0 - lse;
    out[(size_t)node * CC + lane + 32] = l1 - lse;
}

// ---------------- launch ----------------
extern "C" void kernel_launch(void* const* d_in, const int* in_sizes, int n_in,
                              void* d_out, int out_size) {
    const float* x     = (const float*)d_in[0];
    const int*   ei    = (const int*)d_in[1];
    const int*   et    = (const int*)d_in[2];
    const float* W1    = (const float*)d_in[3];
    const float* q1    = (const float*)d_in[4];
    const float* k1    = (const float*)d_in[5];
    const float* b1    = (const float*)d_in[6];
    const float* W2    = (const float*)d_in[7];
    const float* q2    = (const float*)d_in[8];
    const float* k2    = (const float*)d_in[9];
    const float* b2    = (const float*)d_in[10];
    const float* W3    = (const float*)d_in[11];
    const float* q3    = (const float*)d_in[12];
    const float* k3    = (const float*)d_in[13];
    const float* b3    = (const float*)d_in[14];
    const float* lin_w = (const float*)d_in[15];
    const float* lin_b = (const float*)d_in[16];

    float *h1, *h2;
    cudaGetSymbolAddress((void**)&h1, g_h1);
    cudaGetSymbolAddress((void**)&h2, g_h2);

    dim3 wc_grid(4, 4, 8), wc_blk(32, 8);
    dim3 gemm_grid((NN + 127) / 128, RR);

    // ordered so capture slot (-s 5 == my index 3) hits k_gemm (layer 1)
    k_xconv<<<(NN * HH / 2 + 255) / 256, 256>>>(x);            // 0
    k_wconv<<<wc_grid, wc_blk>>>(W1);                          // 1
    k_zero_deg<<<(NN + 255) / 256, 256>>>();                   // 2
    k_gemm<<<gemm_grid, 256>>>();                              // 3  <- profiled
    k_count<<<(EE + 255) / 256, 256>>>(ei);                    // 4
    k_scan1<<<SCAN_B, 1024>>>();                               // 5
    k_scan2<<<1, 64>>>();                                      // 6
    k_scan3<<<SCAN_B, 1024>>>();                               // 7
    k_fill<<<(EE + 255) / 256, 256>>>(ei, et);                 // 8
    k_wqk<<<(RR * FF * 32) / 256, 256>>>(W1, q1, k1);          // 9
    k_qx<<<(NN + 7) / 8, 256>>>(x);                            // 10
    k_agg<<<(NN + 7) / 8, 256>>>(b1, h1);                      // 11

    // ---- layer 2 ----
    k_wconv<<<wc_grid, wc_blk>>>(W2);
    k_wqk<<<(RR * FF * 32) / 256, 256>>>(W2, q2, k2);
    k_qx<<<(NN + 7) / 8, 256>>>(h1);
    k_gemm<<<gemm_grid, 256>>>();
    k_agg<<<(NN + 7) / 8, 256>>>(b2, h2);

    // ---- layer 3 ----
    k_wconv<<<wc_grid, wc_blk>>>(W3);
    k_wqk<<<(RR * FF * 32) / 256, 256>>>(W3, q3, k3);
    k_qx<<<(NN + 7) / 8, 256>>>(h2);
    k_gemm<<<gemm_grid, 256>>>();
    k_agg<<<(NN + 7) / 8, 256>>>(b3, h1);

    k_out<<<(NN + 7) / 8, 256>>>(h1, lin_w, lin_b, (float*)d_out);
}